// round 6
// baseline (speedup 1.0000x reference)
#include <cuda_runtime.h>
#include <cstdint>

#define DIMN   1024
#define BSZ    4
#define LSEQ   8192
#define MROWS  (BSZ * LSEQ)          // 32768
#define GATE_ELEMS ((size_t)MROWS * DIMN)

#define NCHUNK 128
#define TCH    64                    // NCHUNK * TCH == LSEQ

// ---------------- scratch (device globals: allocation-free) ----------------
__device__ float g_z[(size_t)4 * MROWS * DIMN];        // 536 MB: zf, zi, zig, zog
__device__ float g_Ac[BSZ * NCHUNK * DIMN];            // per-chunk prod(f)
__device__ float g_Bc[BSZ * NCHUNK * DIMN];            // per-chunk scan tail
__device__ float g_h0[BSZ * NCHUNK * DIMN];            // per-chunk carry-in h

// ---------------- helpers ----------------
__device__ __forceinline__ unsigned f2tf32(float f) {
    unsigned u;
    asm("cvt.rna.tf32.f32 %0, %1;" : "=r"(u) : "f"(f));
    return u;
}

__device__ __forceinline__ float sigm(float x) {
    return 1.0f / (1.0f + __expf(-x));
}

__device__ __forceinline__ float tanh_acc(float x) {
    x = fminf(fmaxf(x, -15.0f), 15.0f);
    float e = __expf(2.0f * x);
    return (e - 1.0f) / (e + 1.0f);
}

__device__ __forceinline__ void mma_tf32(float c[4], const unsigned a[4], const unsigned b[2]) {
    asm volatile(
        "mma.sync.aligned.m16n8k8.row.col.f32.tf32.tf32.f32 "
        "{%0,%1,%2,%3}, {%4,%5,%6,%7}, {%8,%9}, {%0,%1,%2,%3};\n"
        : "+f"(c[0]), "+f"(c[1]), "+f"(c[2]), "+f"(c[3])
        : "r"(a[0]), "r"(a[1]), "r"(a[2]), "r"(a[3]), "r"(b[0]), "r"(b[1]));
}

// ---------------- GEMM: z[g] = X @ W[g] + bias[g]  (tf32 tensor cores) -----
// Block tile 128x128, K-step 32, 256 threads (8 warps: 2(M) x 4(N), warp 64x32)
// gridDim.x = 32 -> (gate = x & 3, ntile = x >> 2) so that the 4 gates + 8
// n-tiles for one M-tile are adjacent in schedule (x tile stays hot in L2).
#define A_STRIDE 36
#define B_STRIDE 136

__global__ void __launch_bounds__(256, 1) gemm_gates(
    const float* __restrict__ X,
    const float* __restrict__ W0, const float* __restrict__ W1,
    const float* __restrict__ W2, const float* __restrict__ W3,
    const float* __restrict__ b0, const float* __restrict__ b1,
    const float* __restrict__ b2, const float* __restrict__ b3)
{
    const int g    = blockIdx.x & 3;
    const int nblk = blockIdx.x >> 2;

    const float* W    = (g == 0) ? W0 : (g == 1) ? W1 : (g == 2) ? W2 : W3;
    const float* bias = (g == 0) ? b0 : (g == 1) ? b1 : (g == 2) ? b2 : b3;
    float* Z = g_z + (size_t)g * GATE_ELEMS;

    __shared__ unsigned As[128 * A_STRIDE];
    __shared__ unsigned Bs[32 * B_STRIDE];

    const int tid  = threadIdx.x;
    const int lane = tid & 31;
    const int wid  = tid >> 5;
    const int wm   = (wid >> 2) * 64;   // warp M offset within block
    const int wn   = (wid & 3) * 32;    // warp N offset within block
    const int gr   = lane >> 2;         // 0..7
    const int tg   = lane & 3;          // 0..3

    const size_t gm = (size_t)blockIdx.y * 128;
    const int    gn = nblk * 128;

    const float4* X4 = (const float4*)X;
    const float4* W4 = (const float4*)W;

    float acc[4][4][4];
    #pragma unroll
    for (int mt = 0; mt < 4; mt++)
        #pragma unroll
        for (int nt = 0; nt < 4; nt++)
            #pragma unroll
            for (int j = 0; j < 4; j++) acc[mt][nt][j] = 0.0f;

    float4 ra[4], rb[4];
    // prologue: stage k-tile 0
    #pragma unroll
    for (int i = 0; i < 4; i++) {
        int lin = i * 256 + tid;
        ra[i] = X4[(gm + (lin >> 3)) * (DIMN / 4) + (lin & 7)];
        rb[i] = W4[(size_t)(lin >> 5) * (DIMN / 4) + (gn >> 2) + (lin & 31)];
    }

    for (int kt = 0; kt < 32; kt++) {
        // staged regs -> smem (convert to tf32)
        #pragma unroll
        for (int i = 0; i < 4; i++) {
            int lin = i * 256 + tid;
            int row = lin >> 3, c4 = lin & 7;
            uint4 u;
            u.x = f2tf32(ra[i].x); u.y = f2tf32(ra[i].y);
            u.z = f2tf32(ra[i].z); u.w = f2tf32(ra[i].w);
            *(uint4*)&As[row * A_STRIDE + c4 * 4] = u;
            int kr = lin >> 5, n4 = lin & 31;
            uint4 v;
            v.x = f2tf32(rb[i].x); v.y = f2tf32(rb[i].y);
            v.z = f2tf32(rb[i].z); v.w = f2tf32(rb[i].w);
            *(uint4*)&Bs[kr * B_STRIDE + n4 * 4] = v;
        }
        __syncthreads();

        // prefetch next k-tile (overlaps the MMA work below)
        if (kt < 31) {
            #pragma unroll
            for (int i = 0; i < 4; i++) {
                int lin = i * 256 + tid;
                ra[i] = X4[(gm + (lin >> 3)) * (DIMN / 4) + (kt + 1) * 8 + (lin & 7)];
                rb[i] = W4[(size_t)((kt + 1) * 32 + (lin >> 5)) * (DIMN / 4) + (gn >> 2) + (lin & 31)];
            }
        }

        #pragma unroll
        for (int kk = 0; kk < 4; kk++) {
            const int k0 = kk * 8;
            unsigned af[4][4], bf[4][2];
            #pragma unroll
            for (int mt = 0; mt < 4; mt++) {
                int r = wm + mt * 16 + gr;
                af[mt][0] = As[r * A_STRIDE + k0 + tg];
                af[mt][1] = As[(r + 8) * A_STRIDE + k0 + tg];
                af[mt][2] = As[r * A_STRIDE + k0 + tg + 4];
                af[mt][3] = As[(r + 8) * A_STRIDE + k0 + tg + 4];
            }
            #pragma unroll
            for (int nt = 0; nt < 4; nt++) {
                int n = wn + nt * 8 + gr;
                bf[nt][0] = Bs[(k0 + tg) * B_STRIDE + n];
                bf[nt][1] = Bs[(k0 + tg + 4) * B_STRIDE + n];
            }
            #pragma unroll
            for (int mt = 0; mt < 4; mt++)
                #pragma unroll
                for (int nt = 0; nt < 4; nt++)
                    mma_tf32(acc[mt][nt], af[mt], bf[nt]);
        }
        __syncthreads();
    }

    // epilogue: add bias, store z
    #pragma unroll
    for (int mt = 0; mt < 4; mt++) {
        #pragma unroll
        for (int nt = 0; nt < 4; nt++) {
            int r = wm + mt * 16 + gr;
            int n = gn + wn + nt * 8 + 2 * tg;
            float bv0 = bias[n];
            float bv1 = bias[n + 1];
            float2 v0, v1;
            v0.x = acc[mt][nt][0] + bv0; v0.y = acc[mt][nt][1] + bv1;
            v1.x = acc[mt][nt][2] + bv0; v1.y = acc[mt][nt][3] + bv1;
            *(float2*)(Z + (gm + r) * (size_t)DIMN + n)     = v0;
            *(float2*)(Z + (gm + r + 8) * (size_t)DIMN + n) = v1;
        }
    }
}

// ---------------- scan pass 1: per-chunk (A = prod f, B = local scan tail) --
__global__ void scan_reduce()
{
    const int d = blockIdx.x * 256 + threadIdx.x;
    const int c = blockIdx.y;
    const int b = blockIdx.z;
    const size_t base = ((size_t)(b * LSEQ + c * TCH)) * DIMN + d;
    const float* zf = g_z + base;
    const float* zi = g_z + GATE_ELEMS + base;
    const float* zg = g_z + 2 * GATE_ELEMS + base;

    float a = 1.0f, bb = 0.0f;
    #pragma unroll 4
    for (int t = 0; t < TCH; t++) {
        float f  = sigm(zf[t * DIMN]);
        float iv = tanh_acc(zi[t * DIMN]) * sigm(zg[t * DIMN]);
        a *= f;
        bb = fmaf(f, bb, iv);
    }
    int o = (b * NCHUNK + c) * DIMN + d;
    g_Ac[o] = a;
    g_Bc[o] = bb;
}

// ---------------- scan pass 2: sequential combine over chunks ---------------
__global__ void scan_combine(const float* __restrict__ hinit)
{
    const int b = blockIdx.x;
    const int d = threadIdx.x;
    float h = hinit[d];
    for (int c = 0; c < NCHUNK; c++) {
        int o = (b * NCHUNK + c) * DIMN + d;
        g_h0[o] = h;
        h = fmaf(g_Ac[o], h, g_Bc[o]);
    }
}

// ---------------- scan pass 3: apply with carry-in, write y -----------------
__global__ void scan_apply(float* __restrict__ Y)
{
    const int d = blockIdx.x * 256 + threadIdx.x;
    const int c = blockIdx.y;
    const int b = blockIdx.z;
    const size_t base = ((size_t)(b * LSEQ + c * TCH)) * DIMN + d;
    const float* zf = g_z + base;
    const float* zi = g_z + GATE_ELEMS + base;
    const float* zg = g_z + 2 * GATE_ELEMS + base;
    const float* zo = g_z + 3 * GATE_ELEMS + base;

    float h = g_h0[(b * NCHUNK + c) * DIMN + d];
    #pragma unroll 4
    for (int t = 0; t < TCH; t++) {
        float f  = sigm(zf[t * DIMN]);
        float iv = tanh_acc(zi[t * DIMN]) * sigm(zg[t * DIMN]);
        h = fmaf(f, h, iv);
        Y[base + (size_t)t * DIMN] = tanh_acc(h) * sigm(zo[t * DIMN]);
    }
}

// ---------------- launch ----------------------------------------------------
extern "C" void kernel_launch(void* const* d_in, const int* in_sizes, int n_in,
                              void* d_out, int out_size)
{
    (void)in_sizes; (void)n_in; (void)out_size;
    const float* x   = (const float*)d_in[0];
    const float* Wf  = (const float*)d_in[1];
    const float* bf  = (const float*)d_in[2];
    const float* Wi  = (const float*)d_in[3];
    const float* bi  = (const float*)d_in[4];
    const float* Wig = (const float*)d_in[5];
    const float* big = (const float*)d_in[6];
    const float* Wog = (const float*)d_in[7];
    const float* bog = (const float*)d_in[8];
    const float* h0  = (const float*)d_in[9];
    float* y = (float*)d_out;

    // 4 gates x 8 n-tiles in grid.x (keeps x M-tile hot in L2), 256 M-tiles
    gemm_gates<<<dim3(32, MROWS / 128, 1), 256>>>(x, Wf, Wi, Wig, Wog, bf, bi, big, bog);
    scan_reduce<<<dim3(DIMN / 256, NCHUNK, BSZ), 256>>>();
    scan_combine<<<BSZ, DIMN>>>(h0);
    scan_apply<<<dim3(DIMN / 256, NCHUNK, BSZ), 256>>>(y);
}